// round 10
// baseline (speedup 1.0000x reference)
#include <cuda_runtime.h>
#include <math.h>

#define BATCH 64
#define NOBJ 16
#define NPRI 5460
#define NCLS 81
#define NCAND 49
#define NROWS (BATCH * NPRI)
#define TOTAL_ELEMS (NROWS * NCLS)     // 28,304,640

#define GRID_BLOCKS   888              // 148 SMs x 6 blocks
#define ASSIGN_BLOCKS 128              // blocks 0..127: 8 warps = 1024 (b,o)
#define CHUNK         2048             // 256 threads x 8 elems
#define NTICKETS      ((TOTAL_ELEMS + CHUNK - 1) / CHUNK)   // 13821

// zero-initialized at module load; every launch leaves them zeroed (self-clean)
__device__ int      g_winner[NROWS];   // winner+1; 0 = background
__device__ double   g_conf;
__device__ double   g_loc;
__device__ int      g_cnt;
__device__ unsigned g_done;
__device__ unsigned g_abar;            // assign-phase completion counter
__device__ unsigned g_ticket;          // stream chunk ticket counter

// ---------------------------------------------------------------------------
// fast reciprocal: magic init + 2 Newton (rel err ~1.4e-6)
// ---------------------------------------------------------------------------
__device__ __forceinline__ float recip_fast(float v) {
    float y = __int_as_float(0x7EF311C3 - __float_as_int(v));
    y = y * (2.0f - v * y);
    y = y * (2.0f - v * y);
    return y;
}

// ---------------------------------------------------------------------------
// focal helpers — u = e^x formulation (branch-free), base-2 log fold.
// ---------------------------------------------------------------------------
#define LN2_F    0.6931471805599453f
#define LOG2E_F  1.4426950408889634f

__device__ __forceinline__ float focal_nt(float x) {
    const float u = __expf(x);             // MUFU EX2
    const float A = 1.0f + u;
    const float r = recip_fast(A);
    const float s = u * r;                 // sigmoid(x)
    const float L2 = __log2f(A);           // MUFU LG2
    return (0.75f * LN2_F) * (s * s) * L2;
}
__device__ __forceinline__ float focal_t(float x) {
    const float u = __expf(x);
    const float A = 1.0f + u;
    const float r = recip_fast(A);         // 1 - sigmoid(x)
    const float L2 = __log2f(A);
    return (0.25f * LN2_F) * (r * r) * (L2 - x * LOG2E_F);
}

__device__ __forceinline__ float warp_sum(float v) {
#pragma unroll
    for (int off = 16; off; off >>= 1) v += __shfl_xor_sync(0xffffffffu, v, off);
    return v;
}

// ---------------------------------------------------------------------------
// THE kernel: assign (blocks 0..127) -> dynamic-ticket focal stream (all) ->
// abar wait -> per-row correction (all) -> shared last-block finalize.
// ---------------------------------------------------------------------------
__global__ void __launch_bounds__(256, 6) fused_kernel(
        const float* __restrict__ locs,
        const float* __restrict__ boxes,
        const float* __restrict__ scores,
        const int*   __restrict__ labels,
        float* __restrict__ out) {
    __shared__ int   s_cand[8][NCAND];
    __shared__ int   s_auxw[8][NCAND];
    __shared__ float s_pov [8][NCAND];
    __shared__ int   s_t;
    __shared__ float ws[8];
    __shared__ bool  isLast;

    const int tid  = threadIdx.x;
    const int wl   = tid >> 5;
    const int lane = tid & 31;

    // ================= Phase A: ATSS assignment =================
    if (blockIdx.x < ASSIGN_BLOCKS) {
        const int wglob = blockIdx.x * 8 + wl;     // 0..1023
        const int b     = wglob >> 4;
        const int o     = wglob & 15;

        const float4 bb = __ldg(reinterpret_cast<const float4*>(boxes) + (b * NOBJ + o));
        const float bx1 = bb.x, by1 = bb.y, bx2 = bb.z, by2 = bb.w;
        const float bcx = (bx1 + bx2) * 0.5f;
        const float bcy = (by1 + by2) * 0.5f;
        const float area_a = (bx2 - bx1) * (by2 - by1);

        const float FINF = __int_as_float(0x7f800000);
        const int fms[6]   = {64, 32, 16, 8, 4, 2};
        const int bases[6] = {0, 4096, 5120, 5376, 5440, 5456};

        int slot = 0;
#pragma unroll
        for (int l = 0; l < 6; l++) {
            const int fm   = fms[l];
            const int base = bases[l];
            const int w    = (fm < 5) ? fm : 5;
            const int nc   = w * w;
            const int k    = (fm * fm < 9) ? fm * fm : 9;

            int ic = (int)(bcx * (float)fm); ic = min(max(ic, 0), fm - 1);
            int jc = (int)(bcy * (float)fm); jc = min(max(jc, 0), fm - 1);
            const int lox = min(max(ic - 2, 0), fm - w);
            const int loy = min(max(jc - 2, 0), fm - w);

            float d    = FINF;
            int   pidx = 0x7fffffff;
            int   ix = 0, iy = 0;
            if (lane < nc) {
                const int ux = lane % w, uy = lane / w;
                ix = lox + ux; iy = loy + uy;
                const float pcx = ((float)ix + 0.5f) / (float)fm;
                const float pcy = ((float)iy + 0.5f) / (float)fm;
                const float dx = bcx - pcx, dy = bcy - pcy;
                d    = sqrtf(dx * dx + dy * dy);
                pidx = iy * fm + ix;
            }

            int rank = 0;
#pragma unroll
            for (int j = 0; j < nc; j++) {
                const float dj = __shfl_sync(0xffffffffu, d, j);
                const int   pj = __shfl_sync(0xffffffffu, pidx, j);
                rank += (dj < d) | ((dj == d) & (pj < pidx));
            }
            if (lane < nc && rank < k) {
                s_cand[wl][slot + rank] = base + pidx;
                s_auxw[wl][slot + rank] = (fm << 20) | (iy << 10) | ix;
            }
            slot += k;
        }
        __syncwarp();

#pragma unroll
        for (int pass = 0; pass < 2; pass++) {
            const int c = lane + pass * 32;
            if (c < NCAND) {
                const int aux = s_auxw[wl][c];
                const int fm  = aux >> 20;
                const int iy  = (aux >> 10) & 1023, ix = aux & 1023;
                const float pcx = ((float)ix + 0.5f) / (float)fm;
                const float pcy = ((float)iy + 0.5f) / (float)fm;
                const float pwh = 1.5f / (float)fm;
                const float px1 = pcx - pwh * 0.5f, py1 = pcy - pwh * 0.5f;
                const float px2 = pcx + pwh * 0.5f, py2 = pcy + pwh * 0.5f;
                const float tlx = fmaxf(bx1, px1), tly = fmaxf(by1, py1);
                const float brx = fminf(bx2, px2), bry = fminf(by2, py2);
                const float inter = fmaxf(brx - tlx, 0.0f) * fmaxf(bry - tly, 0.0f);
                const float area_b = (px2 - px1) * (py2 - py1);
                s_pov[wl][c] = inter / (area_a + area_b - inter + 1e-10f);
            }
        }
        __syncwarp();

        float p0 = (lane < NCAND) ? s_pov[wl][lane] : 0.0f;
        float p1 = (lane + 32 < NCAND) ? s_pov[wl][lane + 32] : 0.0f;
        const float mean = warp_sum(p0 + p1) / 49.0f;
        float d0 = (lane < NCAND) ? (p0 - mean) : 0.0f;
        float d1 = (lane + 32 < NCAND) ? (p1 - mean) : 0.0f;
        const float ss = warp_sum(d0 * d0 + d1 * d1);
        const float thresh = mean + sqrtf(ss / 48.0f);

        float lloc = 0.0f;
        int   lcnt = 0;
#pragma unroll
        for (int pass = 0; pass < 2; pass++) {
            const int c = lane + pass * 32;
            if (c < NCAND) {
                const int aux = s_auxw[wl][c];
                const int fm  = aux >> 20;
                const int iy  = (aux >> 10) & 1023, ix = aux & 1023;
                const float pcx = ((float)ix + 0.5f) / (float)fm;
                const float pcy = ((float)iy + 0.5f) / (float)fm;
                const float pwh = 1.5f / (float)fm;
                const bool inside = (bx1 <= pcx) && (pcx <= bx2) && (by1 <= pcy) && (pcy <= by2);
                if (inside && (s_pov[wl][c] > thresh)) {
                    const int g = s_cand[wl][c];
                    atomicMax(&g_winner[b * NPRI + g], o + 1);
                    const float4 gl = __ldg(reinterpret_cast<const float4*>(locs) + ((size_t)b * NPRI + g));
                    const float dcx = (gl.x * pwh) / 10.0f + pcx;
                    const float dcy = (gl.y * pwh) / 10.0f + pcy;
                    const float dw  = expf(gl.z / 5.0f) * pwh;
                    const float dh  = expf(gl.w / 5.0f) * pwh;
                    const float px1 = dcx - dw * 0.5f, py1 = dcy - dh * 0.5f;
                    const float px2 = dcx + dw * 0.5f, py2 = dcy + dh * 0.5f;
                    const float tlx = fmaxf(px1, bx1), tly = fmaxf(py1, by1);
                    const float brx = fminf(px2, bx2), bry = fminf(py2, by2);
                    const float inter = fmaxf(brx - tlx, 0.0f) * fmaxf(bry - tly, 0.0f);
                    const float ap = fmaxf(px2 - px1, 0.0f) * fmaxf(py2 - py1, 0.0f);
                    const float iou = inter / (ap + area_a - inter + 1e-7f);
                    const float cpx = (px1 + px2) * 0.5f, cpy = (py1 + py2) * 0.5f;
                    const float ddx = cpx - bcx, ddy = cpy - bcy;
                    const float d2 = ddx * ddx + ddy * ddy;
                    const float etlx = fminf(px1, bx1), etly = fminf(py1, by1);
                    const float ebrx = fmaxf(px2, bx2), ebry = fmaxf(py2, by2);
                    const float ex = ebrx - etlx, ey = ebry - etly;
                    const float diag2 = ex * ex + ey * ey + 1e-7f;
                    lloc += 1.0f - iou + d2 / diag2;
                    lcnt += 1;
                }
            }
        }
#pragma unroll
        for (int off = 16; off; off >>= 1) {
            lloc += __shfl_down_sync(0xffffffffu, lloc, off);
            lcnt += __shfl_down_sync(0xffffffffu, lcnt, off);
        }
        if (lane == 0 && lcnt > 0) {
            atomicAdd(&g_loc, (double)lloc);
            atomicAdd(&g_cnt, lcnt);
        }
        __syncthreads();
        if (tid == 0) {
            __threadfence();
            atomicAdd(&g_abar, 1u);
        }
    }

    // ================= Phase B: focal stream via dynamic tickets =============
    float sum = 0.0f;
    for (;;) {
        if (tid == 0) s_t = (int)atomicAdd(&g_ticket, 1u);
        __syncthreads();
        const int t = s_t;
        __syncthreads();
        if (t >= NTICKETS) break;
        const int i = t * CHUNK + tid * 8;
        if (i < TOTAL_ELEMS) {
            const float4 a = *reinterpret_cast<const float4*>(scores + i);
            const float4 c = *reinterpret_cast<const float4*>(scores + i + 4);
            sum += focal_nt(a.x) + focal_nt(a.y) + focal_nt(a.z) + focal_nt(a.w);
            sum += focal_nt(c.x) + focal_nt(c.y) + focal_nt(c.z) + focal_nt(c.w);
        }
    }

    // ================= Phase C: wait for assignment, then correction =========
    if (tid == 0) {
        while (atomicAdd(&g_abar, 0u) < ASSIGN_BLOCKS) __nanosleep(128);
    }
    __syncthreads();
    __threadfence();

    const int nthr = GRID_BLOCKS * 256;
    for (int row = blockIdx.x * 256 + tid; row < NROWS; row += nthr) {
        const int w = g_winner[row];
        g_winner[row] = 0;                       // self-clean for next replay
        const int cls = (w > 0) ? __ldg(&labels[(row / NPRI) * NOBJ + (w - 1)]) : 0;
        const float x = __ldg(scores + (size_t)row * NCLS + cls);
        sum += focal_t(x) - focal_nt(x);
    }

    // ================= Shared reduce + last-block finalize ===================
#pragma unroll
    for (int off = 16; off; off >>= 1) sum += __shfl_down_sync(0xffffffffu, sum, off);
    if (lane == 0) ws[wl] = sum;
    __syncthreads();
    if (wl == 0) {
        sum = (lane < 8) ? ws[lane] : 0.0f;
#pragma unroll
        for (int off = 4; off; off >>= 1) sum += __shfl_down_sync(0xffffffffu, sum, off);
        if (lane == 0) {
            atomicAdd(&g_conf, (double)sum);
            __threadfence();
            const unsigned t = atomicAdd(&g_done, 1u);
            isLast = (t == GRID_BLOCKS - 1);
        }
    }
    __syncthreads();
    if (isLast && tid == 0) {
        __threadfence();
        const double conf = g_conf / (double)NROWS;
        const double loc  = g_loc / fmax((double)g_cnt, 1.0);
        out[0] = (float)(conf + loc);
        g_conf = 0.0; g_loc = 0.0; g_cnt = 0;
        g_done = 0u; g_abar = 0u; g_ticket = 0u;
    }
}

// ---------------------------------------------------------------------------
extern "C" void kernel_launch(void* const* d_in, const int* in_sizes, int n_in,
                              void* d_out, int out_size) {
    const float* locs   = (const float*)d_in[0];
    const float* scores = (const float*)d_in[1];
    const float* boxes  = (const float*)d_in[2];
    const int*   labels = (const int*)d_in[3];

    fused_kernel<<<GRID_BLOCKS, 256>>>(locs, boxes, scores, labels, (float*)d_out);
}

// round 11
// speedup vs baseline: 1.2253x; 1.2253x over previous
#include <cuda_runtime.h>
#include <math.h>
#include <stdint.h>

#define BATCH 64
#define NOBJ 16
#define NPRI 5460
#define NCLS 81
#define NCAND 49
#define NROWS (BATCH * NPRI)

#define STREAM_BLOCKS 1184
#define CORR_BLOCKS   512
#define TOTAL_DONE    (STREAM_BLOCKS + CORR_BLOCKS)

// zero-initialized at module load; every launch leaves them zeroed (self-clean)
__device__ int      g_winner[NROWS];   // winner+1; 0 = background
__device__ double   g_conf;
__device__ double   g_loc;
__device__ int      g_cnt;
__device__ unsigned g_done;

#define LN2_F    0.6931471805599453f
#define LOG2E_F  1.4426950408889634f

// ---------------------------------------------------------------------------
// packed f32x2 primitives (Blackwell sm_103a; PTX-only, ptxas won't auto-fuse)
// ---------------------------------------------------------------------------
__device__ __forceinline__ uint64_t pack2(float lo, float hi) {
    uint64_t r; asm("mov.b64 %0, {%1, %2};" : "=l"(r) : "f"(lo), "f"(hi)); return r;
}
__device__ __forceinline__ uint64_t mul2(uint64_t a, uint64_t b) {
    uint64_t r; asm("mul.rn.f32x2 %0, %1, %2;" : "=l"(r) : "l"(a), "l"(b)); return r;
}
__device__ __forceinline__ uint64_t fma2(uint64_t a, uint64_t b, uint64_t c) {
    uint64_t r; asm("fma.rn.f32x2 %0, %1, %2, %3;" : "=l"(r) : "l"(a), "l"(b), "l"(c)); return r;
}
__device__ __forceinline__ void unpack2(uint64_t v, float& lo, float& hi) {
    asm("mov.b64 {%0, %1}, %2;" : "=f"(lo), "=f"(hi) : "l"(v));
}

// ---------------------------------------------------------------------------
// fast reciprocal (scalar): magic init + 2 Newton (rel err ~1.4e-6)
// ---------------------------------------------------------------------------
__device__ __forceinline__ float recip_fast(float v) {
    float y = __int_as_float(0x7EF311C3 - __float_as_int(v));
    y = y * (2.0f - v * y);
    y = y * (2.0f - v * y);
    return y;
}

// scalar focal helpers (corr kernel)
__device__ __forceinline__ float focal_nt(float x) {
    const float u = __expf(x);
    const float A = 1.0f + u;
    const float r = recip_fast(A);
    const float s = u * r;                 // sigmoid(x)
    const float L2 = __log2f(A);
    return (0.75f * LN2_F) * (s * s) * L2;
}
__device__ __forceinline__ float focal_t(float x) {
    const float u = __expf(x);
    const float A = 1.0f + u;
    const float r = recip_fast(A);         // 1 - sigmoid(x)
    const float L2 = __log2f(A);
    return (0.25f * LN2_F) * (r * r) * (L2 - x * LOG2E_F);
}

// packed pair: acc += s(x0)^2*log2(A0), s(x1)^2*log2(A1)  (constant factored out)
__device__ __forceinline__ void focal_nt2(float x0, float x1, uint64_t& acc,
                                          uint64_t TWO2, uint64_t NEG12) {
    const float u0 = __expf(x0);
    const float u1 = __expf(x1);
    const float A0 = 1.0f + u0;
    const float A1 = 1.0f + u1;
    const float y0 = __int_as_float(0x7EF311C3 - __float_as_int(A0));
    const float y1 = __int_as_float(0x7EF311C3 - __float_as_int(A1));
    const uint64_t A    = pack2(A0, A1);
    const uint64_t negA = mul2(A, NEG12);
    uint64_t y = pack2(y0, y1);
    y = mul2(y, fma2(negA, y, TWO2));      // NR iter 1
    y = mul2(y, fma2(negA, y, TWO2));      // NR iter 2  -> 1/A
    const uint64_t s  = mul2(pack2(u0, u1), y);     // sigmoid pair
    const uint64_t s2 = mul2(s, s);
    const uint64_t L  = pack2(__log2f(A0), __log2f(A1));
    acc = fma2(s2, L, acc);
}

__device__ __forceinline__ float warp_sum(float v) {
#pragma unroll
    for (int off = 16; off; off >>= 1) v += __shfl_xor_sync(0xffffffffu, v, off);
    return v;
}

// shared tail: block-reduce sum into g_conf, then last-block-done finalize
__device__ __forceinline__ void reduce_and_finalize(float sum, float* out) {
    __shared__ float ws[8];
    __shared__ bool  isLast;
    const int lane = threadIdx.x & 31;
    const int wid  = threadIdx.x >> 5;
#pragma unroll
    for (int off = 16; off; off >>= 1) sum += __shfl_down_sync(0xffffffffu, sum, off);
    if (lane == 0) ws[wid] = sum;
    __syncthreads();
    if (wid == 0) {
        sum = (lane < 8) ? ws[lane] : 0.0f;
#pragma unroll
        for (int off = 4; off; off >>= 1) sum += __shfl_down_sync(0xffffffffu, sum, off);
        if (lane == 0) {
            atomicAdd(&g_conf, (double)sum);
            __threadfence();
            const unsigned t = atomicAdd(&g_done, 1u);
            isLast = (t == TOTAL_DONE - 1);
        }
    }
    __syncthreads();
    if (isLast && threadIdx.x == 0) {
        __threadfence();
        const double conf = g_conf / (double)NROWS;
        const double loc  = g_loc / fmax((double)g_cnt, 1.0);
        out[0] = (float)(conf + loc);
        g_conf = 0.0; g_loc = 0.0; g_cnt = 0; g_done = 0u;
    }
}

// ---------------------------------------------------------------------------
// Kernel 1: ATSS assignment — one WARP per (image, object). Analytic grid
// priors; top-9 per level lie in the clamped 5x5 window around nearest cell.
// ---------------------------------------------------------------------------
__global__ void assign_kernel(const float* __restrict__ locs,
                              const float* __restrict__ boxes) {
    __shared__ int   s_cand[4][NCAND];
    __shared__ int   s_aux [4][NCAND];
    __shared__ float s_pov [4][NCAND];

    const int wl    = threadIdx.x >> 5;
    const int lane  = threadIdx.x & 31;
    const int wglob = blockIdx.x * 4 + wl;
    const int b     = wglob >> 4;
    const int o     = wglob & 15;

    const float4 bb = __ldg(reinterpret_cast<const float4*>(boxes) + (b * NOBJ + o));
    const float bx1 = bb.x, by1 = bb.y, bx2 = bb.z, by2 = bb.w;
    const float bcx = (bx1 + bx2) * 0.5f;
    const float bcy = (by1 + by2) * 0.5f;
    const float area_a = (bx2 - bx1) * (by2 - by1);

    const float FINF = __int_as_float(0x7f800000);
    const int fms[6]   = {64, 32, 16, 8, 4, 2};
    const int bases[6] = {0, 4096, 5120, 5376, 5440, 5456};

    int slot = 0;
#pragma unroll
    for (int l = 0; l < 6; l++) {
        const int fm   = fms[l];
        const int base = bases[l];
        const int w    = (fm < 5) ? fm : 5;
        const int nc   = w * w;
        const int k    = (fm * fm < 9) ? fm * fm : 9;

        int ic = (int)(bcx * (float)fm); ic = min(max(ic, 0), fm - 1);
        int jc = (int)(bcy * (float)fm); jc = min(max(jc, 0), fm - 1);
        const int lox = min(max(ic - 2, 0), fm - w);
        const int loy = min(max(jc - 2, 0), fm - w);

        float d    = FINF;
        int   pidx = 0x7fffffff;
        int   ix = 0, iy = 0;
        if (lane < nc) {
            const int ux = lane % w, uy = lane / w;
            ix = lox + ux; iy = loy + uy;
            const float pcx = ((float)ix + 0.5f) / (float)fm;
            const float pcy = ((float)iy + 0.5f) / (float)fm;
            const float dx = bcx - pcx, dy = bcy - pcy;
            d    = sqrtf(dx * dx + dy * dy);
            pidx = iy * fm + ix;
        }

        int rank = 0;
#pragma unroll
        for (int j = 0; j < nc; j++) {
            const float dj = __shfl_sync(0xffffffffu, d, j);
            const int   pj = __shfl_sync(0xffffffffu, pidx, j);
            rank += (dj < d) | ((dj == d) & (pj < pidx));
        }
        if (lane < nc && rank < k) {
            s_cand[wl][slot + rank] = base + pidx;
            s_aux [wl][slot + rank] = (fm << 20) | (iy << 10) | ix;
        }
        slot += k;
    }
    __syncwarp();

#pragma unroll
    for (int pass = 0; pass < 2; pass++) {
        const int c = lane + pass * 32;
        if (c < NCAND) {
            const int aux = s_aux[wl][c];
            const int fm  = aux >> 20;
            const int iy  = (aux >> 10) & 1023, ix = aux & 1023;
            const float pcx = ((float)ix + 0.5f) / (float)fm;
            const float pcy = ((float)iy + 0.5f) / (float)fm;
            const float pwh = 1.5f / (float)fm;
            const float px1 = pcx - pwh * 0.5f, py1 = pcy - pwh * 0.5f;
            const float px2 = pcx + pwh * 0.5f, py2 = pcy + pwh * 0.5f;
            const float tlx = fmaxf(bx1, px1), tly = fmaxf(by1, py1);
            const float brx = fminf(bx2, px2), bry = fminf(by2, py2);
            const float inter = fmaxf(brx - tlx, 0.0f) * fmaxf(bry - tly, 0.0f);
            const float area_b = (px2 - px1) * (py2 - py1);
            s_pov[wl][c] = inter / (area_a + area_b - inter + 1e-10f);
        }
    }
    __syncwarp();

    float p0 = (lane < NCAND) ? s_pov[wl][lane] : 0.0f;
    float p1 = (lane + 32 < NCAND) ? s_pov[wl][lane + 32] : 0.0f;
    const float mean = warp_sum(p0 + p1) / 49.0f;
    float d0 = (lane < NCAND) ? (p0 - mean) : 0.0f;
    float d1 = (lane + 32 < NCAND) ? (p1 - mean) : 0.0f;
    const float ss = warp_sum(d0 * d0 + d1 * d1);
    const float thresh = mean + sqrtf(ss / 48.0f);

    float lloc = 0.0f;
    int   lcnt = 0;
#pragma unroll
    for (int pass = 0; pass < 2; pass++) {
        const int c = lane + pass * 32;
        if (c < NCAND) {
            const int aux = s_aux[wl][c];
            const int fm  = aux >> 20;
            const int iy  = (aux >> 10) & 1023, ix = aux & 1023;
            const float pcx = ((float)ix + 0.5f) / (float)fm;
            const float pcy = ((float)iy + 0.5f) / (float)fm;
            const float pwh = 1.5f / (float)fm;
            const bool inside = (bx1 <= pcx) && (pcx <= bx2) && (by1 <= pcy) && (pcy <= by2);
            if (inside && (s_pov[wl][c] > thresh)) {
                const int g = s_cand[wl][c];
                atomicMax(&g_winner[b * NPRI + g], o + 1);
                const float4 gl = __ldg(reinterpret_cast<const float4*>(locs) + ((size_t)b * NPRI + g));
                const float dcx = (gl.x * pwh) / 10.0f + pcx;
                const float dcy = (gl.y * pwh) / 10.0f + pcy;
                const float dw  = expf(gl.z / 5.0f) * pwh;
                const float dh  = expf(gl.w / 5.0f) * pwh;
                const float px1 = dcx - dw * 0.5f, py1 = dcy - dh * 0.5f;
                const float px2 = dcx + dw * 0.5f, py2 = dcy + dh * 0.5f;
                const float tlx = fmaxf(px1, bx1), tly = fmaxf(py1, by1);
                const float brx = fminf(px2, bx2), bry = fminf(py2, by2);
                const float inter = fmaxf(brx - tlx, 0.0f) * fmaxf(bry - tly, 0.0f);
                const float ap = fmaxf(px2 - px1, 0.0f) * fmaxf(py2 - py1, 0.0f);
                const float iou = inter / (ap + area_a - inter + 1e-7f);
                const float cpx = (px1 + px2) * 0.5f, cpy = (py1 + py2) * 0.5f;
                const float ddx = cpx - bcx, ddy = cpy - bcy;
                const float d2 = ddx * ddx + ddy * ddy;
                const float etlx = fminf(px1, bx1), etly = fminf(py1, by1);
                const float ebrx = fmaxf(px2, bx2), ebry = fmaxf(py2, by2);
                const float ex = ebrx - etlx, ey = ebry - etly;
                const float diag2 = ex * ex + ey * ey + 1e-7f;
                lloc += 1.0f - iou + d2 / diag2;
                lcnt += 1;
            }
        }
    }
#pragma unroll
    for (int off = 16; off; off >>= 1) {
        lloc += __shfl_down_sync(0xffffffffu, lloc, off);
        lcnt += __shfl_down_sync(0xffffffffu, lcnt, off);
    }
    if (lane == 0 && lcnt > 0) {
        atomicAdd(&g_loc, (double)lloc);
        atomicAdd(&g_cnt, lcnt);
    }
}

// ---------------------------------------------------------------------------
// Kernel 2: streaming focal — packed f32x2 math, constant factored out.
// ---------------------------------------------------------------------------
__global__ void stream_kernel(const float* __restrict__ scores, float* __restrict__ out) {
    const int total = NROWS * NCLS;           // 28,304,640, divisible by 8
    const int nthr  = gridDim.x * blockDim.x;
    const uint64_t TWO2  = pack2(2.0f, 2.0f);
    const uint64_t NEG12 = pack2(-1.0f, -1.0f);
    uint64_t acc = pack2(0.0f, 0.0f);
    for (int i = (blockIdx.x * blockDim.x + threadIdx.x) * 8; i < total; i += nthr * 8) {
        const float4 a = *reinterpret_cast<const float4*>(scores + i);
        const float4 c = *reinterpret_cast<const float4*>(scores + i + 4);
        focal_nt2(a.x, a.y, acc, TWO2, NEG12);
        focal_nt2(a.z, a.w, acc, TWO2, NEG12);
        focal_nt2(c.x, c.y, acc, TWO2, NEG12);
        focal_nt2(c.z, c.w, acc, TWO2, NEG12);
    }
    float a0, a1;
    unpack2(acc, a0, a1);
    reduce_and_finalize((0.75f * LN2_F) * (a0 + a1), out);
}

// ---------------------------------------------------------------------------
// Kernel 3: correction + self-clean (runs concurrently with stream_kernel)
// ---------------------------------------------------------------------------
__global__ void corr_kernel(const float* __restrict__ scores,
                            const int* __restrict__ labels,
                            float* __restrict__ out) {
    const int nthr = gridDim.x * blockDim.x;
    float v = 0.0f;
    for (int row = blockIdx.x * blockDim.x + threadIdx.x; row < NROWS; row += nthr) {
        const int w = g_winner[row];
        g_winner[row] = 0;                       // self-clean for next replay
        const int cls = (w > 0) ? __ldg(&labels[(row / NPRI) * NOBJ + (w - 1)]) : 0;
        const float x = __ldg(scores + (size_t)row * NCLS + cls);
        v += focal_t(x) - focal_nt(x);
    }
    reduce_and_finalize(v, out);
}

// ---------------------------------------------------------------------------
extern "C" void kernel_launch(void* const* d_in, const int* in_sizes, int n_in,
                              void* d_out, int out_size) {
    const float* locs   = (const float*)d_in[0];
    const float* scores = (const float*)d_in[1];
    const float* boxes  = (const float*)d_in[2];
    const int*   labels = (const int*)d_in[3];

    // one-time host-side resources (no device memory involved)
    static cudaStream_t s_aux = nullptr;
    static cudaEvent_t  ev_fork = nullptr, ev_join = nullptr;
    if (s_aux == nullptr) {
        cudaStreamCreateWithFlags(&s_aux, cudaStreamNonBlocking);
        cudaEventCreateWithFlags(&ev_fork, cudaEventDisableTiming);
        cudaEventCreateWithFlags(&ev_join, cudaEventDisableTiming);
    }

    // fork: aux stream runs assign -> corr, overlapping the stream kernel.
    // Finalization is a shared last-block-done over both reduction kernels.
    cudaEventRecord(ev_fork, 0);
    cudaStreamWaitEvent(s_aux, ev_fork, 0);
    assign_kernel<<<256, 128, 0, s_aux>>>(locs, boxes);
    corr_kernel<<<CORR_BLOCKS, 256, 0, s_aux>>>(scores, labels, (float*)d_out);
    cudaEventRecord(ev_join, s_aux);

    stream_kernel<<<STREAM_BLOCKS, 256>>>(scores, (float*)d_out);

    // join aux back into the origin stream (required for graph capture)
    cudaStreamWaitEvent(0, ev_join, 0);
}

// round 12
// speedup vs baseline: 1.2489x; 1.0192x over previous
#include <cuda_runtime.h>
#include <math.h>
#include <stdint.h>

#define BATCH 64
#define NOBJ 16
#define NPRI 5460
#define NCLS 81
#define NCAND 49
#define NROWS (BATCH * NPRI)

#define STREAM_BLOCKS 1184
#define AUX_BLOCKS    64
#define TOTAL_DONE    (STREAM_BLOCKS + AUX_BLOCKS)

// zero-initialized; every launch leaves them zeroed (self-clean)
__device__ double   g_conf;
__device__ double   g_loc;
__device__ int      g_cnt;
__device__ unsigned g_done;

#define LN2_F    0.6931471805599453f
#define LOG2E_F  1.4426950408889634f

// ---------------------------------------------------------------------------
// packed f32x2 primitives (Blackwell sm_103a; PTX-only)
// ---------------------------------------------------------------------------
__device__ __forceinline__ uint64_t pack2(float lo, float hi) {
    uint64_t r; asm("mov.b64 %0, {%1, %2};" : "=l"(r) : "f"(lo), "f"(hi)); return r;
}
__device__ __forceinline__ uint64_t mul2(uint64_t a, uint64_t b) {
    uint64_t r; asm("mul.rn.f32x2 %0, %1, %2;" : "=l"(r) : "l"(a), "l"(b)); return r;
}
__device__ __forceinline__ uint64_t fma2(uint64_t a, uint64_t b, uint64_t c) {
    uint64_t r; asm("fma.rn.f32x2 %0, %1, %2, %3;" : "=l"(r) : "l"(a), "l"(b), "l"(c)); return r;
}
__device__ __forceinline__ void unpack2(uint64_t v, float& lo, float& hi) {
    asm("mov.b64 {%0, %1}, %2;" : "=f"(lo), "=f"(hi) : "l"(v));
}

// ---------------------------------------------------------------------------
// fast reciprocal (scalar): magic init + 2 Newton
// ---------------------------------------------------------------------------
__device__ __forceinline__ float recip_fast(float v) {
    float y = __int_as_float(0x7EF311C3 - __float_as_int(v));
    y = y * (2.0f - v * y);
    y = y * (2.0f - v * y);
    return y;
}

// scalar focal helpers (correction phase)
__device__ __forceinline__ float focal_nt(float x) {
    const float u = __expf(x);
    const float A = 1.0f + u;
    const float r = recip_fast(A);
    const float s = u * r;
    const float L2 = __log2f(A);
    return (0.75f * LN2_F) * (s * s) * L2;
}
__device__ __forceinline__ float focal_t(float x) {
    const float u = __expf(x);
    const float A = 1.0f + u;
    const float r = recip_fast(A);
    const float L2 = __log2f(A);
    return (0.25f * LN2_F) * (r * r) * (L2 - x * LOG2E_F);
}

// packed pair: acc += s(x)^2*log2(1+e^x) for two lanes (constant factored out)
__device__ __forceinline__ void focal_nt2(float x0, float x1, uint64_t& acc,
                                          uint64_t TWO2, uint64_t NEG12) {
    const float u0 = __expf(x0);
    const float u1 = __expf(x1);
    const float A0 = 1.0f + u0;
    const float A1 = 1.0f + u1;
    const float y0 = __int_as_float(0x7EF311C3 - __float_as_int(A0));
    const float y1 = __int_as_float(0x7EF311C3 - __float_as_int(A1));
    const uint64_t A    = pack2(A0, A1);
    const uint64_t negA = mul2(A, NEG12);
    uint64_t y = pack2(y0, y1);
    y = mul2(y, fma2(negA, y, TWO2));
    y = mul2(y, fma2(negA, y, TWO2));
    const uint64_t s  = mul2(pack2(u0, u1), y);
    const uint64_t s2 = mul2(s, s);
    const uint64_t L  = pack2(__log2f(A0), __log2f(A1));
    acc = fma2(s2, L, acc);
}

__device__ __forceinline__ float warp_sum(float v) {
#pragma unroll
    for (int off = 16; off; off >>= 1) v += __shfl_xor_sync(0xffffffffu, v, off);
    return v;
}

// block-reduce sum into g_conf + shared last-block-done finalize (any blockDim)
__device__ __forceinline__ void reduce_and_finalize(float sum, float* out) {
    __shared__ float rws[16];
    __shared__ bool  isLast;
    const int lane = threadIdx.x & 31;
    const int wid  = threadIdx.x >> 5;
    const int nw   = blockDim.x >> 5;
#pragma unroll
    for (int off = 16; off; off >>= 1) sum += __shfl_down_sync(0xffffffffu, sum, off);
    if (lane == 0) rws[wid] = sum;
    __syncthreads();
    if (wid == 0) {
        sum = (lane < nw) ? rws[lane] : 0.0f;
#pragma unroll
        for (int off = 8; off; off >>= 1) sum += __shfl_down_sync(0xffffffffu, sum, off);
        if (lane == 0) {
            atomicAdd(&g_conf, (double)sum);
            __threadfence();
            const unsigned t = atomicAdd(&g_done, 1u);
            isLast = (t == TOTAL_DONE - 1);
        }
    }
    __syncthreads();
    if (isLast && threadIdx.x == 0) {
        __threadfence();
        const double conf = g_conf / (double)NROWS;
        const double loc  = g_loc / fmax((double)g_cnt, 1.0);
        out[0] = (float)(conf + loc);
        g_conf = 0.0; g_loc = 0.0; g_cnt = 0; g_done = 0u;
    }
}

// ---------------------------------------------------------------------------
// Kernel 1 (aux): ONE BLOCK PER IMAGE. 16 warps = 16 objects do ATSS assignment
// with the winner array in SHARED memory, then the same block does the focal
// correction for its image's 5460 rows. No global barrier, no global winner.
// ---------------------------------------------------------------------------
__global__ void __launch_bounds__(512) aux_kernel(
        const float* __restrict__ locs,
        const float* __restrict__ boxes,
        const float* __restrict__ scores,
        const int*   __restrict__ labels,
        float* __restrict__ out) {
    __shared__ int   s_win [NPRI];         // winner+1; 0 = background
    __shared__ int   s_cand[16][NCAND];
    __shared__ int   s_aux [16][NCAND];
    __shared__ float s_pov [16][NCAND];

    const int b    = blockIdx.x;
    const int tid  = threadIdx.x;
    const int wl   = tid >> 5;             // warp = object 0..15
    const int lane = tid & 31;
    const int o    = wl;

    // zero smem winner
    for (int i = tid; i < NPRI; i += 512) s_win[i] = 0;

    const float4 bb = __ldg(reinterpret_cast<const float4*>(boxes) + (b * NOBJ + o));
    const float bx1 = bb.x, by1 = bb.y, bx2 = bb.z, by2 = bb.w;
    const float bcx = (bx1 + bx2) * 0.5f;
    const float bcy = (by1 + by2) * 0.5f;
    const float area_a = (bx2 - bx1) * (by2 - by1);

    const float FINF = __int_as_float(0x7f800000);
    const int fms[6]   = {64, 32, 16, 8, 4, 2};
    const int bases[6] = {0, 4096, 5120, 5376, 5440, 5456};

    int slot = 0;
#pragma unroll
    for (int l = 0; l < 6; l++) {
        const int fm   = fms[l];
        const int base = bases[l];
        const int w    = (fm < 5) ? fm : 5;
        const int nc   = w * w;
        const int k    = (fm * fm < 9) ? fm * fm : 9;

        int ic = (int)(bcx * (float)fm); ic = min(max(ic, 0), fm - 1);
        int jc = (int)(bcy * (float)fm); jc = min(max(jc, 0), fm - 1);
        const int lox = min(max(ic - 2, 0), fm - w);
        const int loy = min(max(jc - 2, 0), fm - w);

        float d    = FINF;
        int   pidx = 0x7fffffff;
        int   ix = 0, iy = 0;
        if (lane < nc) {
            const int ux = lane % w, uy = lane / w;
            ix = lox + ux; iy = loy + uy;
            const float pcx = ((float)ix + 0.5f) / (float)fm;
            const float pcy = ((float)iy + 0.5f) / (float)fm;
            const float dx = bcx - pcx, dy = bcy - pcy;
            d    = sqrtf(dx * dx + dy * dy);
            pidx = iy * fm + ix;
        }

        int rank = 0;
#pragma unroll
        for (int j = 0; j < nc; j++) {
            const float dj = __shfl_sync(0xffffffffu, d, j);
            const int   pj = __shfl_sync(0xffffffffu, pidx, j);
            rank += (dj < d) | ((dj == d) & (pj < pidx));
        }
        if (lane < nc && rank < k) {
            s_cand[wl][slot + rank] = base + pidx;
            s_aux [wl][slot + rank] = (fm << 20) | (iy << 10) | ix;
        }
        slot += k;
    }
    __syncwarp();

#pragma unroll
    for (int pass = 0; pass < 2; pass++) {
        const int c = lane + pass * 32;
        if (c < NCAND) {
            const int aux = s_aux[wl][c];
            const int fm  = aux >> 20;
            const int iy  = (aux >> 10) & 1023, ix = aux & 1023;
            const float pcx = ((float)ix + 0.5f) / (float)fm;
            const float pcy = ((float)iy + 0.5f) / (float)fm;
            const float pwh = 1.5f / (float)fm;
            const float px1 = pcx - pwh * 0.5f, py1 = pcy - pwh * 0.5f;
            const float px2 = pcx + pwh * 0.5f, py2 = pcy + pwh * 0.5f;
            const float tlx = fmaxf(bx1, px1), tly = fmaxf(by1, py1);
            const float brx = fminf(bx2, px2), bry = fminf(by2, py2);
            const float inter = fmaxf(brx - tlx, 0.0f) * fmaxf(bry - tly, 0.0f);
            const float area_b = (px2 - px1) * (py2 - py1);
            s_pov[wl][c] = inter / (area_a + area_b - inter + 1e-10f);
        }
    }
    __syncwarp();

    float p0 = (lane < NCAND) ? s_pov[wl][lane] : 0.0f;
    float p1 = (lane + 32 < NCAND) ? s_pov[wl][lane + 32] : 0.0f;
    const float mean = warp_sum(p0 + p1) / 49.0f;
    float dv0 = (lane < NCAND) ? (p0 - mean) : 0.0f;
    float dv1 = (lane + 32 < NCAND) ? (p1 - mean) : 0.0f;
    const float ss = warp_sum(dv0 * dv0 + dv1 * dv1);
    const float thresh = mean + sqrtf(ss / 48.0f);

    // barrier: s_win zeroing (all threads) must complete before atomics
    __syncthreads();

    float lloc = 0.0f;
    int   lcnt = 0;
#pragma unroll
    for (int pass = 0; pass < 2; pass++) {
        const int c = lane + pass * 32;
        if (c < NCAND) {
            const int aux = s_aux[wl][c];
            const int fm  = aux >> 20;
            const int iy  = (aux >> 10) & 1023, ix = aux & 1023;
            const float pcx = ((float)ix + 0.5f) / (float)fm;
            const float pcy = ((float)iy + 0.5f) / (float)fm;
            const float pwh = 1.5f / (float)fm;
            const bool inside = (bx1 <= pcx) && (pcx <= bx2) && (by1 <= pcy) && (pcy <= by2);
            if (inside && (s_pov[wl][c] > thresh)) {
                const int g = s_cand[wl][c];
                atomicMax(&s_win[g], o + 1);
                const float4 gl = __ldg(reinterpret_cast<const float4*>(locs) + ((size_t)b * NPRI + g));
                const float dcx = (gl.x * pwh) / 10.0f + pcx;
                const float dcy = (gl.y * pwh) / 10.0f + pcy;
                const float dw  = expf(gl.z / 5.0f) * pwh;
                const float dh  = expf(gl.w / 5.0f) * pwh;
                const float px1 = dcx - dw * 0.5f, py1 = dcy - dh * 0.5f;
                const float px2 = dcx + dw * 0.5f, py2 = dcy + dh * 0.5f;
                const float tlx = fmaxf(px1, bx1), tly = fmaxf(py1, by1);
                const float brx = fminf(px2, bx2), bry = fminf(py2, by2);
                const float inter = fmaxf(brx - tlx, 0.0f) * fmaxf(bry - tly, 0.0f);
                const float ap = fmaxf(px2 - px1, 0.0f) * fmaxf(py2 - py1, 0.0f);
                const float iou = inter / (ap + area_a - inter + 1e-7f);
                const float cpx = (px1 + px2) * 0.5f, cpy = (py1 + py2) * 0.5f;
                const float ddx = cpx - bcx, ddy = cpy - bcy;
                const float d2 = ddx * ddx + ddy * ddy;
                const float etlx = fminf(px1, bx1), etly = fminf(py1, by1);
                const float ebrx = fmaxf(px2, bx2), ebry = fmaxf(py2, by2);
                const float ex = ebrx - etlx, ey = ebry - etly;
                const float diag2 = ex * ex + ey * ey + 1e-7f;
                lloc += 1.0f - iou + d2 / diag2;
                lcnt += 1;
            }
        }
    }
#pragma unroll
    for (int off = 16; off; off >>= 1) {
        lloc += __shfl_down_sync(0xffffffffu, lloc, off);
        lcnt += __shfl_down_sync(0xffffffffu, lcnt, off);
    }
    if (lane == 0 && lcnt > 0) {
        atomicAdd(&g_loc, (double)lloc);
        atomicAdd(&g_cnt, lcnt);
    }

    // winners complete -> correction for this image's rows
    __syncthreads();

    float v = 0.0f;
    const int lab_base = b * NOBJ;
    for (int g = tid; g < NPRI; g += 512) {
        const int w = s_win[g];
        const int cls = (w > 0) ? __ldg(&labels[lab_base + (w - 1)]) : 0;
        const float x = __ldg(scores + ((size_t)b * NPRI + g) * NCLS + cls);
        v += focal_t(x) - focal_nt(x);
    }
    reduce_and_finalize(v, out);
}

// ---------------------------------------------------------------------------
// Kernel 2: streaming focal — packed f32x2 math, 16 elems/iter.
// ---------------------------------------------------------------------------
__global__ void stream_kernel(const float* __restrict__ scores, float* __restrict__ out) {
    const int total = NROWS * NCLS;           // 28,304,640, divisible by 16
    const int nthr  = gridDim.x * blockDim.x;
    const uint64_t TWO2  = pack2(2.0f, 2.0f);
    const uint64_t NEG12 = pack2(-1.0f, -1.0f);
    uint64_t acc = pack2(0.0f, 0.0f);
    for (int i = (blockIdx.x * blockDim.x + threadIdx.x) * 16; i < total; i += nthr * 16) {
        const float4 a = *reinterpret_cast<const float4*>(scores + i);
        const float4 c = *reinterpret_cast<const float4*>(scores + i + 4);
        const float4 e = *reinterpret_cast<const float4*>(scores + i + 8);
        const float4 f = *reinterpret_cast<const float4*>(scores + i + 12);
        focal_nt2(a.x, a.y, acc, TWO2, NEG12);
        focal_nt2(a.z, a.w, acc, TWO2, NEG12);
        focal_nt2(c.x, c.y, acc, TWO2, NEG12);
        focal_nt2(c.z, c.w, acc, TWO2, NEG12);
        focal_nt2(e.x, e.y, acc, TWO2, NEG12);
        focal_nt2(e.z, e.w, acc, TWO2, NEG12);
        focal_nt2(f.x, f.y, acc, TWO2, NEG12);
        focal_nt2(f.z, f.w, acc, TWO2, NEG12);
    }
    float a0, a1;
    unpack2(acc, a0, a1);
    reduce_and_finalize((0.75f * LN2_F) * (a0 + a1), out);
}

// ---------------------------------------------------------------------------
extern "C" void kernel_launch(void* const* d_in, const int* in_sizes, int n_in,
                              void* d_out, int out_size) {
    const float* locs   = (const float*)d_in[0];
    const float* scores = (const float*)d_in[1];
    const float* boxes  = (const float*)d_in[2];
    const int*   labels = (const int*)d_in[3];

    // one-time host-side resources (no device memory involved)
    static cudaStream_t s_aux = nullptr;
    static cudaEvent_t  ev_fork = nullptr, ev_join = nullptr;
    if (s_aux == nullptr) {
        cudaStreamCreateWithFlags(&s_aux, cudaStreamNonBlocking);
        cudaEventCreateWithFlags(&ev_fork, cudaEventDisableTiming);
        cudaEventCreateWithFlags(&ev_join, cudaEventDisableTiming);
    }

    // fork: aux stream runs the per-image assign+corr kernel, overlapping the
    // stream kernel. Finalization is a shared last-block-done over both.
    cudaEventRecord(ev_fork, 0);
    cudaStreamWaitEvent(s_aux, ev_fork, 0);
    aux_kernel<<<AUX_BLOCKS, 512, 0, s_aux>>>(locs, boxes, scores, labels, (float*)d_out);
    cudaEventRecord(ev_join, s_aux);

    stream_kernel<<<STREAM_BLOCKS, 256>>>(scores, (float*)d_out);

    // join aux back into the origin stream (required for graph capture)
    cudaStreamWaitEvent(0, ev_join, 0);
}